// round 9
// baseline (speedup 1.0000x reference)
#include <cuda_runtime.h>

#define B_  16
#define C_  64
#define H_  224
#define W_  224
#define O_  128
#define PH_ 16
#define OH_ 222
#define OW_ 222
#define HW56 (H_ * 56)

__device__ float g_s[(size_t)B_ * H_ * W_];

// ---------- k1: channel reduction ----------
// Row-paired: thread handles (b,h,col) and (b,h+112,col) — same hh => shared pw.
// grid = B*112*56/128 = 784 blocks x 128 threads.
__global__ __launch_bounds__(128, 5) void k1_reduce(
    const float* __restrict__ x,
    const float* __restrict__ pw,
    const float* __restrict__ pb)
{
    __shared__ float4 bs[64];                 // sum_c pb : 16 hh x 4 float4-cols

    const int t = threadIdx.x;
    if (t < 64) {
        const float4* pb4 = (const float4*)pb;
        float4 a = make_float4(0.f, 0.f, 0.f, 0.f);
        #pragma unroll 16
        for (int c = 0; c < C_; c++) {
            float4 v = __ldg(pb4 + c * 64 + t);
            a.x += v.x; a.y += v.y; a.z += v.z; a.w += v.w;
        }
        bs[t] = a;
    }

    const int p   = blockIdx.x * 128 + t;     // 0 .. B*112*56-1
    const int col = p % 56;
    const int r   = p / 56;
    const int b   = r / 112;
    const int h   = r % 112;                  // second row = h + 112 (same hh)
    const int hh  = h & (PH_ - 1);
    const int w4  = col & 3;

    const float4* xp0 = (const float4*)x + (size_t)b * C_ * HW56
                                         + (size_t)h * 56 + col;
    const float4* xp1 = xp0 + 112 * 56;
    const float4* wp  = (const float4*)pw + hh * 4 + w4;

    __syncthreads();
    float4 acc0 = bs[hh * 4 + w4];
    float4 acc1 = acc0;

    #pragma unroll 2
    for (int c0 = 0; c0 < C_; c0 += 8) {
        float4 xv0[8], xv1[8];
        #pragma unroll
        for (int j = 0; j < 8; j++) {
            xv0[j] = __ldg(xp0 + (size_t)(c0 + j) * HW56);
            xv1[j] = __ldg(xp1 + (size_t)(c0 + j) * HW56);
        }
        #pragma unroll
        for (int j = 0; j < 8; j++) {
            float4 wv = __ldg(wp + (c0 + j) * 64);
            acc0.x = fmaf(xv0[j].x, wv.x, acc0.x);
            acc0.y = fmaf(xv0[j].y, wv.y, acc0.y);
            acc0.z = fmaf(xv0[j].z, wv.z, acc0.z);
            acc0.w = fmaf(xv0[j].w, wv.w, acc0.w);
            acc1.x = fmaf(xv1[j].x, wv.x, acc1.x);
            acc1.y = fmaf(xv1[j].y, wv.y, acc1.y);
            acc1.z = fmaf(xv1[j].z, wv.z, acc1.z);
            acc1.w = fmaf(xv1[j].w, wv.w, acc1.w);
        }
    }
    float4* sp = (float4*)g_s + ((size_t)b * H_ + h) * 56 + col;
    sp[0]        = acc0;
    sp[112 * 56] = acc1;
}

// ---------- k2: 3x3 conv (byte-identical to proven winner) ----------
#define OCG 32
__global__ __launch_bounds__(224) void k2_conv3x3(
    const float* __restrict__ comp,
    float* __restrict__ out)
{
    const int gx = blockIdx.x;
    const int b  = gx / (OH_ / 2);
    const int i0 = (gx % (OH_ / 2)) * 2;
    const int o0 = blockIdx.y * OCG;

    __shared__ float srow[4][W_];
    __shared__ float csh[OCG * 12];

    const int t = threadIdx.x;

    const float* sp = g_s + ((size_t)b * H_ + i0) * W_;
    #pragma unroll
    for (int k = 0; k < 4; k++)
        srow[k][t] = sp[k * W_ + t];
    for (int idx = t; idx < OCG * 9; idx += 224) {
        int k = idx / 9, m = idx % 9;
        csh[k * 12 + m] = comp[(o0 + k) * 9 + m];
    }
    __syncthreads();

    const int r  = t / 112;
    const int q  = t % 112;
    if (q >= 111) return;
    const int j0 = q * 2;
    const int i  = i0 + r;

    float2 va[3], vb[3];
    #pragma unroll
    for (int d = 0; d < 3; d++) {
        va[d] = *(const float2*)&srow[r + d][j0];
        vb[d] = *(const float2*)&srow[r + d][j0 + 2];
    }

    const float4* csh4 = (const float4*)csh;
    size_t base = (((size_t)b * O_ + o0) * OH_ + i) * OW_ + j0;

    #pragma unroll 8
    for (int k = 0; k < OCG; k++) {
        float4 w0 = csh4[k * 3 + 0];
        float4 w1 = csh4[k * 3 + 1];
        float4 w2 = csh4[k * 3 + 2];

        float ax, ay;
        ax = w0.x * va[0].x; ay = w0.x * va[0].y;
        ax = fmaf(w0.y, va[0].y, ax); ay = fmaf(w0.y, vb[0].x, ay);
        ax = fmaf(w0.z, vb[0].x, ax); ay = fmaf(w0.z, vb[0].y, ay);

        ax = fmaf(w0.w, va[1].x, ax); ay = fmaf(w0.w, va[1].y, ay);
        ax = fmaf(w1.x, va[1].y, ax); ay = fmaf(w1.x, vb[1].x, ay);
        ax = fmaf(w1.y, vb[1].x, ax); ay = fmaf(w1.y, vb[1].y, ay);

        ax = fmaf(w1.z, va[2].x, ax); ay = fmaf(w1.z, va[2].y, ay);
        ax = fmaf(w1.w, va[2].y, ax); ay = fmaf(w1.w, vb[2].x, ay);
        ax = fmaf(w2.x, vb[2].x, ax); ay = fmaf(w2.x, vb[2].y, ay);

        *(float2*)(out + base + (size_t)k * (OH_ * OW_)) = make_float2(ax, ay);
    }
}

extern "C" void kernel_launch(void* const* d_in, const int* in_sizes, int n_in,
                              void* d_out, int out_size)
{
    const float* x    = (const float*)d_in[0];
    const float* pw   = (const float*)d_in[1];
    const float* pb   = (const float*)d_in[2];
    const float* comp = (const float*)d_in[3];
    float* out = (float*)d_out;

    k1_reduce<<<(B_ * 112 * 56) / 128, 128>>>(x, pw, pb);
    dim3 g2(B_ * (OH_ / 2), O_ / OCG);
    k2_conv3x3<<<g2, 224>>>(comp, out);
}

// round 10
// speedup vs baseline: 1.0491x; 1.0491x over previous
#include <cuda_runtime.h>

#define B_  16
#define C_  64
#define H_  224
#define W_  224
#define O_  128
#define PH_ 16
#define OH_ 222
#define OW_ 222
#define HW56 (H_ * 56)

__device__ float g_s[(size_t)B_ * H_ * W_];
__constant__ float c_comp[O_ * 9];      // compressor weights, const-space

// ---------- k1: channel reduction (R8 winner, verbatim) ----------
__global__ __launch_bounds__(128, 6) void k1_reduce(
    const float* __restrict__ x,
    const float* __restrict__ pw,
    const float* __restrict__ pb)
{
    __shared__ float4 bs[64];

    const int t = threadIdx.x;
    if (t < 64) {
        const float4* pb4 = (const float4*)pb;
        float4 a = make_float4(0.f, 0.f, 0.f, 0.f);
        #pragma unroll 16
        for (int c = 0; c < C_; c++) {
            float4 v = __ldg(pb4 + c * 64 + t);
            a.x += v.x; a.y += v.y; a.z += v.z; a.w += v.w;
        }
        bs[t] = a;
    }

    const int p   = blockIdx.x * 128 + t;
    const int col = p % 56;
    const int bh  = p / 56;
    const int h   = bh % H_;
    const int hh  = h & (PH_ - 1);
    const int w4  = col & 3;

    const float4* xp = (const float4*)x + (size_t)(bh / H_) * C_ * HW56
                                        + (size_t)h * 56 + col;
    const float4* wp = (const float4*)pw + hh * 4 + w4;

    __syncthreads();
    float4 acc = bs[hh * 4 + w4];

    #pragma unroll 2
    for (int c0 = 0; c0 < C_; c0 += 8) {
        float4 xv[8];
        #pragma unroll
        for (int j = 0; j < 8; j++)
            xv[j] = __ldg(xp + (size_t)(c0 + j) * HW56);
        #pragma unroll
        for (int j = 0; j < 8; j++) {
            float4 wv = __ldg(wp + (c0 + j) * 64);
            acc.x = fmaf(xv[j].x, wv.x, acc.x);
            acc.y = fmaf(xv[j].y, wv.y, acc.y);
            acc.z = fmaf(xv[j].z, wv.z, acc.z);
            acc.w = fmaf(xv[j].w, wv.w, acc.w);
        }
    }
    ((float4*)g_s)[p] = acc;
}

// ---------- k2: 3x3 conv, weights from constant memory ----------
#define OCG 32
__global__ __launch_bounds__(224) void k2_conv3x3(float* __restrict__ out)
{
    const int gx = blockIdx.x;
    const int b  = gx / (OH_ / 2);
    const int i0 = (gx % (OH_ / 2)) * 2;
    const int o0 = blockIdx.y * OCG;

    __shared__ float srow[4][W_];

    const int t = threadIdx.x;

    const float* sp = g_s + ((size_t)b * H_ + i0) * W_;
    #pragma unroll
    for (int k = 0; k < 4; k++)
        srow[k][t] = sp[k * W_ + t];
    __syncthreads();

    const int r  = t / 112;
    const int q  = t % 112;
    if (q >= 111) return;
    const int j0 = q * 2;
    const int i  = i0 + r;

    float2 va[3], vb[3];
    #pragma unroll
    for (int d = 0; d < 3; d++) {
        va[d] = *(const float2*)&srow[r + d][j0];
        vb[d] = *(const float2*)&srow[r + d][j0 + 2];
    }

    const float* cw = c_comp + o0 * 9;
    size_t base = (((size_t)b * O_ + o0) * OH_ + i) * OW_ + j0;

    #pragma unroll 8
    for (int k = 0; k < OCG; k++) {
        const float* w = cw + k * 9;     // warp-uniform const address -> LDCU

        float ax, ay;
        ax = w[0] * va[0].x;          ay = w[0] * va[0].y;
        ax = fmaf(w[1], va[0].y, ax); ay = fmaf(w[1], vb[0].x, ay);
        ax = fmaf(w[2], vb[0].x, ax); ay = fmaf(w[2], vb[0].y, ay);

        ax = fmaf(w[3], va[1].x, ax); ay = fmaf(w[3], va[1].y, ay);
        ax = fmaf(w[4], va[1].y, ax); ay = fmaf(w[4], vb[1].x, ay);
        ax = fmaf(w[5], vb[1].x, ax); ay = fmaf(w[5], vb[1].y, ay);

        ax = fmaf(w[6], va[2].x, ax); ay = fmaf(w[6], va[2].y, ay);
        ax = fmaf(w[7], va[2].y, ax); ay = fmaf(w[7], vb[2].x, ay);
        ax = fmaf(w[8], vb[2].x, ax); ay = fmaf(w[8], vb[2].y, ay);

        *(float2*)(out + base + (size_t)k * (OH_ * OW_)) = make_float2(ax, ay);
    }
}

extern "C" void kernel_launch(void* const* d_in, const int* in_sizes, int n_in,
                              void* d_out, int out_size)
{
    const float* x    = (const float*)d_in[0];
    const float* pw   = (const float*)d_in[1];
    const float* pb   = (const float*)d_in[2];
    const float* comp = (const float*)d_in[3];
    float* out = (float*)d_out;

    // device->constant copy (async D2D, graph-capturable)
    cudaMemcpyToSymbolAsync(c_comp, comp, O_ * 9 * sizeof(float), 0,
                            cudaMemcpyDeviceToDevice, 0);

    k1_reduce<<<(B_ * H_ * 56) / 128, 128>>>(x, pw, pb);
    dim3 g2(B_ * (OH_ / 2), O_ / OCG);
    k2_conv3x3<<<g2, 224>>>(out);
}